// round 6
// baseline (speedup 1.0000x reference)
#include <cuda_runtime.h>
#include <cstdint>
#include <cstddef>

// Problem dims (fixed per reference)
#define BB 256
#define TT 512
#define II 64
#define HH 128
#define GG 512   // 4*H

typedef unsigned long long ull;

// Scratch for precomputed input-gate projections: [B, T, 4H] fp32 = 256 MB.
__device__ float g_xg[(size_t)BB * TT * GG];

__device__ __forceinline__ float fsig(float x) {
    return __fdividef(1.f, 1.f + __expf(-x));
}
__device__ __forceinline__ float ftanh(float x) {
    float e = __expf(2.f * x);
    return 1.f - __fdividef(2.f, e + 1.f);
}

// Packed f32x2 ops (sm_103a; ptxas never auto-fuses these)
__device__ __forceinline__ ull fma2(ull a, ull b, ull c) {
    ull d;
    asm("fma.rn.f32x2 %0, %1, %2, %3;" : "=l"(d) : "l"(a), "l"(b), "l"(c));
    return d;
}
__device__ __forceinline__ ull pack2(float x, float y) {
    ull r;
    asm("mov.b64 %0, {%1, %2};" : "=l"(r) : "f"(x), "f"(y));
    return r;
}
__device__ __forceinline__ float hsum2(ull a) {
    uint2 u = *reinterpret_cast<uint2*>(&a);
    return __uint_as_float(u.x) + __uint_as_float(u.y);
}
__device__ __forceinline__ float lo2(ull a) { return __uint_as_float((unsigned)a); }
__device__ __forceinline__ float hi2(ull a) { return __uint_as_float((unsigned)(a >> 32)); }

// ---------------------------------------------------------------------------
// Kernel 1: x_gates GEMM, f32x2-packed, PERSISTENT blocks (kept from R5 —
// it cut non-scan time 312 -> 234 us). W + bias staged once per block.
// ---------------------------------------------------------------------------
#define NTILES 2048

__global__ __launch_bounds__(512, 1) void xg_gemm(
    const float* __restrict__ X,
    const float* __restrict__ Wih,
    const float* __restrict__ bih,
    const float* __restrict__ bhh)
{
    extern __shared__ __align__(16) float sm[];
    float* Xs = sm;                 // [64][68]  (m-contiguous rows)
    float* Ws = sm + 64 * 68;       // [64][516]
    float* bs = Ws + 64 * 516;      // [512]
    const int tid = threadIdx.x;

    bs[tid] = bih[tid] + bhh[tid];
    for (int idx = tid; idx < 512 * 64; idx += 512) {
        int n = idx >> 6, k = idx & 63;
        Ws[k * 516 + n] = Wih[n * II + k];
    }

    const int ni = tid & 63, mi = tid >> 6;
    const int nb = ni * 8,  mb = mi * 8;

    for (int tile = blockIdx.x; tile < NTILES; tile += gridDim.x) {
        const int m0 = tile * 64;
        __syncthreads();   // previous tile's Xs readers done / Ws staged (1st iter)
        for (int idx = tid; idx < 64 * 64; idx += 512) {
            int m = idx >> 6, k = idx & 63;
            Xs[k * 68 + m] = X[(size_t)(m0 + m) * II + k];
        }
        __syncthreads();

        ull acc2[4][8];
        #pragma unroll
        for (int n = 0; n < 8; n++) {
            float bv = bs[nb + n];
            ull bp = pack2(bv, bv);
            #pragma unroll
            for (int mp = 0; mp < 4; mp++) acc2[mp][n] = bp;
        }

        #pragma unroll 4
        for (int k = 0; k < 64; k++) {
            ulonglong2 a01 = *(const ulonglong2*)&Xs[k * 68 + mb];
            ulonglong2 a23 = *(const ulonglong2*)&Xs[k * 68 + mb + 4];
            ull a[4] = {a01.x, a01.y, a23.x, a23.y};
            float4 b0 = *(const float4*)&Ws[k * 516 + nb];
            float4 b1 = *(const float4*)&Ws[k * 516 + nb + 4];
            float bv[8] = {b0.x, b0.y, b0.z, b0.w, b1.x, b1.y, b1.z, b1.w};
            #pragma unroll
            for (int n = 0; n < 8; n++) {
                ull bb = pack2(bv[n], bv[n]);
                #pragma unroll
                for (int mp = 0; mp < 4; mp++)
                    acc2[mp][n] = fma2(a[mp], bb, acc2[mp][n]);
            }
        }

        #pragma unroll
        for (int mp = 0; mp < 4; mp++) {
            size_t row0 = (size_t)(m0 + mb + 2 * mp);
            float4* o0 = (float4*)&g_xg[row0 * GG + nb];
            float4* o1 = (float4*)&g_xg[(row0 + 1) * GG + nb];
            o0[0] = make_float4(lo2(acc2[mp][0]), lo2(acc2[mp][1]), lo2(acc2[mp][2]), lo2(acc2[mp][3]));
            o0[1] = make_float4(lo2(acc2[mp][4]), lo2(acc2[mp][5]), lo2(acc2[mp][6]), lo2(acc2[mp][7]));
            o1[0] = make_float4(hi2(acc2[mp][0]), hi2(acc2[mp][1]), hi2(acc2[mp][2]), hi2(acc2[mp][3]));
            o1[1] = make_float4(hi2(acc2[mp][4]), hi2(acc2[mp][5]), hi2(acc2[mp][6]), hi2(acc2[mp][7]));
        }
    }
}

// ---------------------------------------------------------------------------
// Kernel 2: LSTM scan — R4 structure (128 blocks x 256 threads, thread owns
// gates tid & tid+256 for both batches), rebuilt for latency hiding:
//  * 4 accumulator chains (not 8)         -> frees 8 regs, shorter tail
//  * KREG=72 (144 weight regs)            -> ~55 spare regs for scheduling
//  * manual prefetch of next-iter weights AND h vectors into temps, with the
//    register-loop h prefetch flowing into the smem loop's first h.
// ---------------------------------------------------------------------------
#define KREG 72                  // k-values per gate held in registers
#define QSH  14                  // (128-KREG)/4 : ulonglong2 smem weight loads

__global__ __launch_bounds__(256, 1) void lstm_scan(
    const float* __restrict__ hprev,
    const float* __restrict__ cprev,
    const float* __restrict__ Whh,
    float* __restrict__ out)
{
    extern __shared__ __align__(16) float sm[];
    ulonglong2* wA = (ulonglong2*)sm;            // [QSH][256]
    ulonglong2* wB = wA + QSH * 256;             // [QSH][256]
    float* h0s = (float*)(wB + QSH * 256);       // [128]
    float* h1s = h0s + 128;                      // [128]
    float* gsm = h1s + 128;                      // [2][512]

    const int tid = threadIdx.x;
    const int b0  = blockIdx.x * 2;
    const int gA  = tid;
    const int gB  = tid + 256;

    // Stage smem weight tail (k = KREG..127) for both gates
    #pragma unroll
    for (int q = 0; q < QSH; q++) {
        wA[q * 256 + tid] = *(const ulonglong2*)&Whh[gA * HH + KREG + 4 * q];
        wB[q * 256 + tid] = *(const ulonglong2*)&Whh[gB * HH + KREG + 4 * q];
    }

    // Register weights: 36 packed pairs per gate
    ull wrA[KREG / 2], wrB[KREG / 2];
    #pragma unroll
    for (int p = 0; p < KREG / 2; p++) {
        wrA[p] = *(const ull*)&Whh[gA * HH + 2 * p];
        wrB[p] = *(const ull*)&Whh[gB * HH + 2 * p];
    }

    // Init h, c : thread owns (b = tid>>7, j = tid&127)
    const int b = tid >> 7, j = tid & 127;
    float* hs = b ? h1s : h0s;
    hs[j] = hprev[(b0 + b) * HH + j];
    float c = cprev[(b0 + b) * HH + j];
    __syncthreads();

    const float* xb0 = g_xg + (size_t)b0 * TT * GG;
    const float* xb1 = xb0 + (size_t)TT * GG;

    // Prefetch t=0 x values
    float x00 = xb0[tid], x01 = xb0[256 + tid];
    float x10 = xb1[tid], x11 = xb1[256 + tid];

    for (int t = 0; t < TT; t++) {
        // Prefetch next step's x (consumed one full GEMV later)
        size_t noff = (size_t)(t + 1 < TT ? t + 1 : t) * GG;
        float n00 = xb0[noff + tid], n01 = xb0[noff + 256 + tid];
        float n10 = xb1[noff + tid], n11 = xb1[noff + 256 + tid];

        // 4 accumulator chains: {gate A,B} x {batch 0,1}
        ull aA0 = 0, aA1 = 0, aB0 = 0, aB1 = 0;

        // h prefetch pipeline
        ulonglong2 h0p = *(const ulonglong2*)&h0s[0];
        ulonglong2 h1p = *(const ulonglong2*)&h1s[0];

        // k = 0..KREG-1 : register weights; h prefetched one iter ahead
        #pragma unroll
        for (int q = 0; q < KREG / 4; q++) {
            ulonglong2 h0 = h0p, h1 = h1p;
            h0p = *(const ulonglong2*)&h0s[4 * (q + 1)];   // q=last -> h[KREG], feeds smem loop
            h1p = *(const ulonglong2*)&h1s[4 * (q + 1)];
            ull w0 = wrA[2 * q], w1 = wrA[2 * q + 1];
            ull v0 = wrB[2 * q], v1 = wrB[2 * q + 1];
            aA0 = fma2(w1, h0.y, fma2(w0, h0.x, aA0));
            aB0 = fma2(v1, h0.y, fma2(v0, h0.x, aB0));
            aA1 = fma2(w1, h1.y, fma2(w0, h1.x, aA1));
            aB1 = fma2(v1, h1.y, fma2(v0, h1.x, aB1));
        }

        // k = KREG..127 : smem weights, both weights and h prefetched ahead
        ulonglong2 wa = wA[tid], wb = wB[tid];
        #pragma unroll
        for (int q = 0; q < QSH; q++) {
            ulonglong2 h0 = h0p, h1 = h1p;
            if (q + 1 < QSH) {
                h0p = *(const ulonglong2*)&h0s[KREG + 4 * (q + 1)];
                h1p = *(const ulonglong2*)&h1s[KREG + 4 * (q + 1)];
            }
            ulonglong2 wan, wbn;
            if (q + 1 < QSH) {
                wan = wA[(q + 1) * 256 + tid];
                wbn = wB[(q + 1) * 256 + tid];
            }
            aA0 = fma2(wa.y, h0.y, fma2(wa.x, h0.x, aA0));
            aB0 = fma2(wb.y, h0.y, fma2(wb.x, h0.x, aB0));
            aA1 = fma2(wa.y, h1.y, fma2(wa.x, h1.x, aA1));
            aB1 = fma2(wb.y, h1.y, fma2(wb.x, h1.x, aB1));
            if (q + 1 < QSH) { wa = wan; wb = wbn; }
        }

        gsm[tid]             = x00 + hsum2(aA0);
        gsm[256 + tid]       = x01 + hsum2(aB0);
        gsm[512 + tid]       = x10 + hsum2(aA1);
        gsm[512 + 256 + tid] = x11 + hsum2(aB1);
        __syncthreads();

        // Cell update: all 256 threads, one (batch, cell) each
        {
            const float* gb = gsm + b * 512;
            float ig = fsig(gb[j]);             // PyTorch order: i, f, g, o
            float fg = fsig(gb[j + 128]);
            float gg = ftanh(gb[j + 256]);
            float og = fsig(gb[j + 384]);
            c = fg * c + ig * gg;
            float h = og * ftanh(c);
            hs[j] = h;
            out[((size_t)(b0 + b) * TT + t) * HH + j] = h;
        }
        __syncthreads();

        x00 = n00; x01 = n01; x10 = n10; x11 = n11;
    }

    // h_last, c_last appended after outputs
    {
        size_t base = (size_t)BB * TT * HH;
        out[base + (b0 + b) * HH + j] = hs[j];
        out[base + (size_t)BB * HH + (b0 + b) * HH + j] = c;
    }
}

// ---------------------------------------------------------------------------
extern "C" void kernel_launch(void* const* d_in, const int* in_sizes, int n_in,
                              void* d_out, int out_size)
{
    const float* inputs = (const float*)d_in[0];
    const float* hprev  = (const float*)d_in[1];
    const float* cprev  = (const float*)d_in[2];
    const float* Wih    = (const float*)d_in[3];
    const float* Whh    = (const float*)d_in[4];
    const float* bih    = (const float*)d_in[5];
    const float* bhh    = (const float*)d_in[6];
    float* out = (float*)d_out;
    (void)in_sizes; (void)n_in; (void)out_size;

    const size_t smem1 = (size_t)(64 * 68 + 64 * 516 + 512) * sizeof(float);     // ~148 KB
    const size_t smem2 = (size_t)(2 * QSH * 256) * sizeof(ulonglong2)
                       + (size_t)(256 + 1024) * sizeof(float);                   // ~117 KB
    cudaFuncSetAttribute(xg_gemm,   cudaFuncAttributeMaxDynamicSharedMemorySize, (int)smem1);
    cudaFuncSetAttribute(lstm_scan, cudaFuncAttributeMaxDynamicSharedMemorySize, (int)smem2);

    xg_gemm  <<<148, 512, smem1>>>(inputs, Wih, bih, bhh);
    lstm_scan<<<128, 256, smem2>>>(hprev, cprev, Whh, out);
}

// round 8
// speedup vs baseline: 1.2560x; 1.2560x over previous
#include <cuda_runtime.h>
#include <cstdint>
#include <cstddef>

// Problem dims (fixed per reference)
#define BB 256
#define TT 512
#define II 64
#define HH 128
#define GG 512   // 4*H

typedef unsigned long long ull;

// Scratch for precomputed input-gate projections: [B, T, 4H] fp32 = 256 MB.
__device__ float g_xg[(size_t)BB * TT * GG];

__device__ __forceinline__ float fsig(float x) {
    return __fdividef(1.f, 1.f + __expf(-x));
}
__device__ __forceinline__ float ftanh(float x) {
    float e = __expf(2.f * x);
    return 1.f - __fdividef(2.f, e + 1.f);
}

// Packed f32x2 ops (sm_103a; ptxas never auto-fuses these)
__device__ __forceinline__ ull fma2(ull a, ull b, ull c) {
    ull d;
    asm("fma.rn.f32x2 %0, %1, %2, %3;" : "=l"(d) : "l"(a), "l"(b), "l"(c));
    return d;
}
__device__ __forceinline__ ull add2(ull a, ull b) {
    ull d;
    asm("add.rn.f32x2 %0, %1, %2;" : "=l"(d) : "l"(a), "l"(b));
    return d;
}
__device__ __forceinline__ ull pack2(float x, float y) {
    ull r;
    asm("mov.b64 %0, {%1, %2};" : "=l"(r) : "f"(x), "f"(y));
    return r;
}
__device__ __forceinline__ float hsum2(ull a) {
    uint2 u = *reinterpret_cast<uint2*>(&a);
    return __uint_as_float(u.x) + __uint_as_float(u.y);
}
__device__ __forceinline__ float lo2(ull a) { return __uint_as_float((unsigned)a); }
__device__ __forceinline__ float hi2(ull a) { return __uint_as_float((unsigned)(a >> 32)); }

// ---------------------------------------------------------------------------
// Kernel 1: x_gates GEMM, f32x2-packed, PERSISTENT blocks (proven in R5/R6).
// ---------------------------------------------------------------------------
#define NTILES 2048

__global__ __launch_bounds__(512, 1) void xg_gemm(
    const float* __restrict__ X,
    const float* __restrict__ Wih,
    const float* __restrict__ bih,
    const float* __restrict__ bhh)
{
    extern __shared__ __align__(16) float sm[];
    float* Xs = sm;                 // [64][68]  (m-contiguous rows)
    float* Ws = sm + 64 * 68;       // [64][516]
    float* bs = Ws + 64 * 516;      // [512]
    const int tid = threadIdx.x;

    bs[tid] = bih[tid] + bhh[tid];
    for (int idx = tid; idx < 512 * 64; idx += 512) {
        int n = idx >> 6, k = idx & 63;
        Ws[k * 516 + n] = Wih[n * II + k];
    }

    const int ni = tid & 63, mi = tid >> 6;
    const int nb = ni * 8,  mb = mi * 8;

    for (int tile = blockIdx.x; tile < NTILES; tile += gridDim.x) {
        const int m0 = tile * 64;
        __syncthreads();   // previous tile's Xs readers done / Ws staged (1st iter)
        for (int idx = tid; idx < 64 * 64; idx += 512) {
            int m = idx >> 6, k = idx & 63;
            Xs[k * 68 + m] = X[(size_t)(m0 + m) * II + k];
        }
        __syncthreads();

        ull acc2[4][8];
        #pragma unroll
        for (int n = 0; n < 8; n++) {
            float bv = bs[nb + n];
            ull bp = pack2(bv, bv);
            #pragma unroll
            for (int mp = 0; mp < 4; mp++) acc2[mp][n] = bp;
        }

        #pragma unroll 4
        for (int k = 0; k < 64; k++) {
            ulonglong2 a01 = *(const ulonglong2*)&Xs[k * 68 + mb];
            ulonglong2 a23 = *(const ulonglong2*)&Xs[k * 68 + mb + 4];
            ull a[4] = {a01.x, a01.y, a23.x, a23.y};
            float4 b0 = *(const float4*)&Ws[k * 516 + nb];
            float4 b1 = *(const float4*)&Ws[k * 516 + nb + 4];
            float bv[8] = {b0.x, b0.y, b0.z, b0.w, b1.x, b1.y, b1.z, b1.w};
            #pragma unroll
            for (int n = 0; n < 8; n++) {
                ull bb = pack2(bv[n], bv[n]);
                #pragma unroll
                for (int mp = 0; mp < 4; mp++)
                    acc2[mp][n] = fma2(a[mp], bb, acc2[mp][n]);
            }
        }

        #pragma unroll
        for (int mp = 0; mp < 4; mp++) {
            size_t row0 = (size_t)(m0 + mb + 2 * mp);
            float4* o0 = (float4*)&g_xg[row0 * GG + nb];
            float4* o1 = (float4*)&g_xg[(row0 + 1) * GG + nb];
            o0[0] = make_float4(lo2(acc2[mp][0]), lo2(acc2[mp][1]), lo2(acc2[mp][2]), lo2(acc2[mp][3]));
            o0[1] = make_float4(lo2(acc2[mp][4]), lo2(acc2[mp][5]), lo2(acc2[mp][6]), lo2(acc2[mp][7]));
            o1[0] = make_float4(hi2(acc2[mp][0]), hi2(acc2[mp][1]), hi2(acc2[mp][2]), hi2(acc2[mp][3]));
            o1[1] = make_float4(hi2(acc2[mp][4]), hi2(acc2[mp][5]), hi2(acc2[mp][6]), hi2(acc2[mp][7]));
        }
    }
}

// ---------------------------------------------------------------------------
// Kernel 2: LSTM scan — R4 skeleton (128 blocks x 256 threads, thread owns
// gates tid & tid+256 for both batches, 8 independent fma2 chains) with:
//  * KREG=72: ~40 spare regs so ptxas can hoist the LDS streams
//  * double-buffered h (read hc, write hn): no intra-step h hazard
//  * 2-warp-group named barrier between GEMV and update. Cells {j, j+128}
//    depend only on threads {j, j+128} = warps {w, w+4}: gsm slots are
//    group-private, so groups stagger through the update tail.
//  * one full __syncthreads per step (publishes hn to all warps)
// ---------------------------------------------------------------------------
#define KREG 72                  // k-values per gate held in registers
#define QSH  14                  // (128-KREG)/4 : ulonglong2 smem weight loads

__global__ __launch_bounds__(256, 1) void lstm_scan(
    const float* __restrict__ hprev,
    const float* __restrict__ cprev,
    const float* __restrict__ Whh,
    float* __restrict__ out)
{
    extern __shared__ __align__(16) float smdyn[];
    ulonglong2* wA = (ulonglong2*)smdyn;         // [QSH][256]
    ulonglong2* wB = wA + QSH * 256;             // [QSH][256]
    float* hbuf = (float*)(wB + QSH * 256);      // [2 buf][2 batch][128]
    float* gsm  = hbuf + 2 * 2 * 128;            // [2][512]

    const int tid = threadIdx.x;
    const int b0  = blockIdx.x * 2;
    const int gA  = tid;
    const int gB  = tid + 256;
    const int barid = 1 + ((tid >> 5) & 3);      // 2-warp group {w, w+4}

    // Stage smem weight tail (k = KREG..127) for both gates
    #pragma unroll
    for (int q = 0; q < QSH; q++) {
        wA[q * 256 + tid] = *(const ulonglong2*)&Whh[gA * HH + KREG + 4 * q];
        wB[q * 256 + tid] = *(const ulonglong2*)&Whh[gB * HH + KREG + 4 * q];
    }

    // Register weights: 36 packed pairs per gate
    ull wrA[KREG / 2], wrB[KREG / 2];
    #pragma unroll
    for (int p = 0; p < KREG / 2; p++) {
        wrA[p] = *(const ull*)&Whh[gA * HH + 2 * p];
        wrB[p] = *(const ull*)&Whh[gB * HH + 2 * p];
    }

    // h double buffers
    float* hc0 = hbuf;             // current, batch 0
    float* hc1 = hbuf + 128;       // current, batch 1
    float* hn0 = hbuf + 256;       // next,    batch 0
    float* hn1 = hbuf + 384;       // next,    batch 1

    // Init h, c : thread owns (b = tid>>7, j = tid&127)
    const int b = tid >> 7, j = tid & 127;
    float h = hprev[(b0 + b) * HH + j];
    float c = cprev[(b0 + b) * HH + j];
    (b ? hc1 : hc0)[j] = h;
    __syncthreads();

    const float* xb0 = g_xg + (size_t)b0 * TT * GG;
    const float* xb1 = xb0 + (size_t)TT * GG;

    // Prefetch t=0 x values
    float x00 = xb0[tid], x01 = xb0[256 + tid];
    float x10 = xb1[tid], x11 = xb1[256 + tid];

    for (int t = 0; t < TT; t++) {
        // Prefetch next step's x (consumed one full GEMV later)
        size_t noff = (size_t)(t + 1 < TT ? t + 1 : t) * GG;
        float n00 = xb0[noff + tid], n01 = xb0[noff + 256 + tid];
        float n10 = xb1[noff + tid], n11 = xb1[noff + 256 + tid];

        // 8 independent accumulator chains: {gate A,B} x {batch 0,1} x {x,y}
        ull aA0x = 0, aA0y = 0, aA1x = 0, aA1y = 0;
        ull aB0x = 0, aB0y = 0, aB1x = 0, aB1y = 0;

        // k = 0..KREG-1 : register weights
        #pragma unroll
        for (int q = 0; q < KREG / 4; q++) {
            ulonglong2 h0 = *(const ulonglong2*)&hc0[4 * q];
            ulonglong2 h1 = *(const ulonglong2*)&hc1[4 * q];
            ull w0 = wrA[2 * q], w1 = wrA[2 * q + 1];
            ull v0 = wrB[2 * q], v1 = wrB[2 * q + 1];
            aA0x = fma2(w0, h0.x, aA0x);  aA0y = fma2(w1, h0.y, aA0y);
            aA1x = fma2(w0, h1.x, aA1x);  aA1y = fma2(w1, h1.y, aA1y);
            aB0x = fma2(v0, h0.x, aB0x);  aB0y = fma2(v1, h0.y, aB0y);
            aB1x = fma2(v0, h1.x, aB1x);  aB1y = fma2(v1, h1.y, aB1y);
        }
        // k = KREG..127 : smem weights
        #pragma unroll
        for (int q = 0; q < QSH; q++) {
            ulonglong2 h0 = *(const ulonglong2*)&hc0[KREG + 4 * q];
            ulonglong2 h1 = *(const ulonglong2*)&hc1[KREG + 4 * q];
            ulonglong2 wa = wA[q * 256 + tid];
            ulonglong2 wb = wB[q * 256 + tid];
            aA0x = fma2(wa.x, h0.x, aA0x);  aA0y = fma2(wa.y, h0.y, aA0y);
            aA1x = fma2(wa.x, h1.x, aA1x);  aA1y = fma2(wa.y, h1.y, aA1y);
            aB0x = fma2(wb.x, h0.x, aB0x);  aB0y = fma2(wb.y, h0.y, aB0y);
            aB1x = fma2(wb.x, h1.x, aB1x);  aB1y = fma2(wb.y, h1.y, aB1y);
        }

        gsm[tid]             = x00 + hsum2(add2(aA0x, aA0y));
        gsm[256 + tid]       = x01 + hsum2(add2(aB0x, aB0y));
        gsm[512 + tid]       = x10 + hsum2(add2(aA1x, aA1y));
        gsm[512 + 256 + tid] = x11 + hsum2(add2(aB1x, aB1y));

        // Group barrier: cells {j, j+128} <- gates from threads {j, j+128}
        // = warps {w, w+4} only. h hazard is gone (update writes hn).
        asm volatile("bar.sync %0, %1;" :: "r"(barid), "r"(64) : "memory");

        // Cell update: all 256 threads, one (batch, cell) each; write h_next
        {
            const float* gb = gsm + b * 512;
            float ig = fsig(gb[j]);             // PyTorch order: i, f, g, o
            float fg = fsig(gb[j + 128]);
            float gg = ftanh(gb[j + 256]);
            float og = fsig(gb[j + 384]);
            c = fg * c + ig * gg;
            h = og * ftanh(c);
            (b ? hn1 : hn0)[j] = h;
            out[((size_t)(b0 + b) * TT + t) * HH + j] = h;
        }
        __syncthreads();   // hn published; all GEMV reads of hc done

        // Swap buffers
        float* s0 = hc0; hc0 = hn0; hn0 = s0;
        float* s1 = hc1; hc1 = hn1; hn1 = s1;

        x00 = n00; x01 = n01; x10 = n10; x11 = n11;
    }

    // h_last, c_last appended after outputs (thread-local h, c)
    {
        size_t base = (size_t)BB * TT * HH;
        out[base + (b0 + b) * HH + j] = h;
        out[base + (size_t)BB * HH + (b0 + b) * HH + j] = c;
    }
}

// ---------------------------------------------------------------------------
extern "C" void kernel_launch(void* const* d_in, const int* in_sizes, int n_in,
                              void* d_out, int out_size)
{
    const float* inputs = (const float*)d_in[0];
    const float* hprev  = (const float*)d_in[1];
    const float* cprev  = (const float*)d_in[2];
    const float* Wih    = (const float*)d_in[3];
    const float* Whh    = (const float*)d_in[4];
    const float* bih    = (const float*)d_in[5];
    const float* bhh    = (const float*)d_in[6];
    float* out = (float*)d_out;
    (void)in_sizes; (void)n_in; (void)out_size;

    const size_t smem1 = (size_t)(64 * 68 + 64 * 516 + 512) * sizeof(float);     // ~148 KB
    const size_t smem2 = (size_t)(2 * QSH * 256) * sizeof(ulonglong2)
                       + (size_t)(2 * 2 * 128 + 2 * 512) * sizeof(float);        // ~118 KB
    cudaFuncSetAttribute(xg_gemm,   cudaFuncAttributeMaxDynamicSharedMemorySize, (int)smem1);
    cudaFuncSetAttribute(lstm_scan, cudaFuncAttributeMaxDynamicSharedMemorySize, (int)smem2);

    xg_gemm  <<<148, 512, smem1>>>(inputs, Wih, bih, bhh);
    lstm_scan<<<128, 256, smem2>>>(hprev, cprev, Whh, out);
}